// round 2
// baseline (speedup 1.0000x reference)
#include <cuda_runtime.h>

#define NV 23
#define NN 529          // 23*23
#define TV 12
#define ROWLEN 6348     // N*N*T = per-batch stride in floats
#define NTHREADS 544    // 17 warps; threads 529..543 inactive (but sync)
#define NBLOCKS 296     // 148 SMs * 2 blocks

__global__ __launch_bounds__(NTHREADS, 2)
void gat_kernel(const float* __restrict__ flow,
                const int*   __restrict__ adj,
                const float* __restrict__ W,
                float*       __restrict__ out,
                int B)
{
    __shared__ float dbuf[2][NN];   // staged data slice d[m*23+i] for current/next batch
    __shared__ int   adj_s[NN];

    const int tid = threadIdx.x;
    const bool act = (tid < NN);
    int i_idx = 0, k_idx = 0;
    if (act) { i_idx = tid / NV; k_idx = tid - i_idx * NV; }

    // ---- adjacency with forced self-loops ----
    if (act) {
        int a = adj[tid];
        if (i_idx == k_idx) a = 1;
        adj_s[tid] = a;
    }
    __syncthreads();

    // ---- per-thread attention row att[i_idx][k_idx][0..22] in registers ----
    float att[NV];
    if (act) {
        const float* wr = W + tid * NV;
        float mn = 0.0f;                       // = min(min_m W, 0)
        #pragma unroll
        for (int m = 0; m < NV; ++m) {
            att[m] = wr[m];
            mn = fminf(mn, att[m]);
        }
        float s = 0.0f;
        #pragma unroll
        for (int m = 0; m < NV; ++m) {
            float a = (adj_s[k_idx * NV + m] != 0) ? (att[m] - mn) : 0.0f;
            att[m] = a;
            s += a;
        }
        float inv = 1.0f / s;
        #pragma unroll
        for (int m = 0; m < NV; ++m) att[m] *= inv;
    }

    // ---- grid-stride batch loop, double-buffered gather of last timestep ----
    int b = blockIdx.x;
    const int stride = gridDim.x;

    // prologue: stage batch b
    float v = 0.0f;
    if (act && b < B)
        v = __ldg(flow + (size_t)b * ROWLEN + tid * TV + (TV - 1));
    if (act) dbuf[0][tid] = v;
    __syncthreads();

    int p = 0;
    for (; b < B; b += stride) {
        const int bn = b + stride;

        // prefetch next batch's 529 scattered elements (32B-sector gather)
        float vn = 0.0f;
        if (act && bn < B)
            vn = __ldg(flow + (size_t)bn * ROWLEN + tid * TV + (TV - 1));

        // compute x[b, i_idx, k_idx] = sum_m att[m] * d[m, i_idx]
        if (act) {
            const float* d = dbuf[p];
            float acc = 0.0f;
            #pragma unroll
            for (int m = 0; m < NV; ++m)
                acc = fmaf(att[m], d[m * NV + i_idx], acc);
            out[(size_t)b * NN + tid] = acc;     // coalesced
        }

        // stage next batch into the other buffer
        if (act) dbuf[p ^ 1][tid] = vn;
        __syncthreads();
        p ^= 1;
    }
}

extern "C" void kernel_launch(void* const* d_in, const int* in_sizes, int n_in,
                              void* d_out, int out_size) {
    const float* flow = (const float*)d_in[0];   // (B, N, N, T) fp32
    const int*   adj  = (const int*)  d_in[1];   // (N, N) int32
    const float* W    = (const float*)d_in[2];   // (N, N, N) fp32
    float*       out  = (float*)d_out;           // (B, N, N, 1) fp32

    const int B = in_sizes[0] / ROWLEN;
    gat_kernel<<<NBLOCKS, NTHREADS>>>(flow, adj, W, out, B);
}